// round 5
// baseline (speedup 1.0000x reference)
#include <cuda_runtime.h>
#include <math.h>

#define NN 2048
#define MM 128
#define KD 8
#define K2 64
#define NPACK 36
#define NPB 16            // children per block
#define NB (NN / NPB)     // 128 chunks per t

// ---------------- scratch --------------------------------------------------
__device__ float4 g_C4[2][11][MM];  // 44 coefs per m: 36 Bp (0.5diag/1.0off) + 8 (-h)
__device__ float  g_dm[2][MM];      // -log|det G| - 4 + 0.5 e.e
__device__ double g_part[2][NB];
__device__ unsigned int g_done;

// ---------------- f32x2 helpers --------------------------------------------
__device__ __forceinline__ void ffma2(unsigned long long& d,
                                      unsigned long long a, unsigned long long b) {
    asm("fma.rn.f32x2 %0, %1, %2, %0;" : "+l"(d) : "l"(a), "l"(b));
}
__device__ __forceinline__ float2 unpack2(unsigned long long v) {
    float2 f;
    asm("mov.b64 {%0, %1}, %2;" : "=f"(f.x), "=f"(f.y) : "l"(v));
    return f;
}

// ==================== parent kernel =========================================
__global__ __launch_bounds__(128)
void parent_kernel(const float* __restrict__ mu_q, const float* __restrict__ sigma_q,
                   const float* __restrict__ omega_parent,
                   const float* __restrict__ mu_s, const float* __restrict__ sigma_s,
                   const float* __restrict__ omega_m_parent) {
    int t = blockIdx.x;
    int m = threadIdx.x;
    if (t == 0 && m == 0) g_done = 0u;
    const float* mup = (t == 0) ? mu_q : mu_s;
    const float* Sp  = (t == 0) ? sigma_q : sigma_s;
    const float* Op  = (t == 0) ? omega_parent : omega_m_parent;

    float __align__(16) S[KD][KD];
    float __align__(16) O[KD][KD];
    float __align__(16) e[KD];
    {
        const float4* s4 = reinterpret_cast<const float4*>(Sp + (size_t)m * K2);
        const float4* o4 = reinterpret_cast<const float4*>(Op + (size_t)m * K2);
        float4* Sd = reinterpret_cast<float4*>(&S[0][0]);
        float4* Od = reinterpret_cast<float4*>(&O[0][0]);
#pragma unroll
        for (int q = 0; q < 16; q++) { Sd[q] = s4[q]; Od[q] = o4[q]; }
        const float4* m4 = reinterpret_cast<const float4*>(mup + (size_t)m * KD);
        reinterpret_cast<float4*>(e)[0] = m4[0];
        reinterpret_cast<float4*>(e)[1] = m4[1];
    }
    // Cholesky in place (lower triangle -> L)
#pragma unroll
    for (int j = 0; j < KD; j++) {
        float s = S[j][j];
#pragma unroll
        for (int k = 0; k < j; k++) s -= S[j][k] * S[j][k];
        float ljj = sqrtf(s);
        S[j][j] = ljj;
        float inv = 1.f / ljj;
#pragma unroll
        for (int i = j + 1; i < KD; i++) {
            float si = S[i][j];
#pragma unroll
            for (int k = 0; k < j; k++) si -= S[i][k] * S[j][k];
            S[i][j] = si * inv;
        }
    }
    // G = L^{-1} O (in place), e := L^{-1} e
#pragma unroll
    for (int i = 0; i < KD; i++) {
        float inv = 1.f / S[i][i];
#pragma unroll
        for (int c = 0; c < KD; c++) {
            float s = O[i][c];
#pragma unroll
            for (int k = 0; k < i; k++) s -= S[i][k] * O[k][c];
            O[i][c] = s * inv;
        }
        float se = e[i];
#pragma unroll
        for (int k = 0; k < i; k++) se -= S[i][k] * e[k];
        e[i] = se * inv;
    }
    // coefs: Bp packed + (-h)
    float cf[44];
    {
        int p = 0;
#pragma unroll
        for (int i = 0; i < KD; i++) {
#pragma unroll
            for (int j = i; j < KD; j++) {
                float b = 0.f;
#pragma unroll
                for (int k = 0; k < KD; k++) b += O[k][i] * O[k][j];
                cf[p++] = (i == j) ? 0.5f * b : b;
            }
        }
    }
    float ee = 0.f;
#pragma unroll
    for (int i = 0; i < KD; i++) {
        float s = 0.f;
#pragma unroll
        for (int k = 0; k < KD; k++) s += O[k][i] * e[k];
        cf[NPACK + i] = -s;
        ee += e[i] * e[i];
    }
#pragma unroll
    for (int q = 0; q < 11; q++)
        g_C4[t][q][m] = make_float4(cf[4 * q], cf[4 * q + 1], cf[4 * q + 2], cf[4 * q + 3]);
    // log|det G| via unpivoted LU
    float pd = 1.f;
#pragma unroll
    for (int j = 0; j < KD; j++) {
        float piv = O[j][j];
        pd *= piv;
        float ip = 1.f / piv;
#pragma unroll
        for (int r = j + 1; r < KD; r++) {
            float f = O[r][j] * ip;
#pragma unroll
            for (int c = j + 1; c < KD; c++) O[r][c] -= f * O[j][c];
        }
    }
    g_dm[t][m] = -logf(fabsf(pd)) - 4.0f + 0.5f * ee;
}

// ==================== child math (writes 48-float record to shared) =========
__device__ __forceinline__ void child_work(int n, const float* __restrict__ muc,
                                           const float* __restrict__ Sc,
                                           const float* __restrict__ Oc,
                                           float* __restrict__ rec) {
    float __align__(16) O[KD][KD];
    float __align__(16) S[KD][KD];
    float __align__(16) mu[KD];
    {
        const float4* s4 = reinterpret_cast<const float4*>(Sc + (size_t)n * K2);
        const float4* o4 = reinterpret_cast<const float4*>(Oc + (size_t)n * K2);
        float4* Sd = reinterpret_cast<float4*>(&S[0][0]);
        float4* Od = reinterpret_cast<float4*>(&O[0][0]);
#pragma unroll
        for (int q = 0; q < 16; q++) { Sd[q] = s4[q]; Od[q] = o4[q]; }
        const float4* m4 = reinterpret_cast<const float4*>(muc + (size_t)n * KD);
        reinterpret_cast<float4*>(mu)[0] = m4[0];
        reinterpret_cast<float4*>(mu)[1] = m4[1];
    }
    // unpivoted Gauss-Jordan inverse; product of pivots = det
    float pd = 1.f;
#pragma unroll
    for (int k = 0; k < KD; k++) {
        float piv = O[k][k];
        pd *= piv;
        float ip = 1.f / piv;
#pragma unroll
        for (int i = 0; i < KD; i++) {
            if (i == k) continue;
            float f = O[i][k] * ip;
#pragma unroll
            for (int j = 0; j < KD; j++)
                if (j != k) O[i][j] -= f * O[k][j];
            O[i][k] = -f;
        }
#pragma unroll
        for (int j = 0; j < KD; j++)
            if (j != k) O[k][j] *= ip;
        O[k][k] = ip;
    }
    float lad = logf(fabsf(pd));

    float out[45];
    float v[KD];
#pragma unroll
    for (int i = 0; i < KD; i++) {
        float s = 0.f;
#pragma unroll
        for (int j = 0; j < KD; j++) s += O[i][j] * mu[j];
        v[i] = s;
        out[NPACK + i] = s;
    }
    // Atilde = Oi S Oi^T + v v^T, packed upper
    {
        int p = 0;
#pragma unroll
        for (int i = 0; i < KD; i++) {
            float trow[KD];
#pragma unroll
            for (int c = 0; c < KD; c++) {
                float s = 0.f;
#pragma unroll
                for (int b = 0; b < KD; b++) s += O[i][b] * S[b][c];
                trow[c] = s;
            }
#pragma unroll
            for (int j = i; j < KD; j++) {
                float a = v[i] * v[j];
#pragma unroll
                for (int c = 0; c < KD; c++) a += trow[c] * O[j][c];
                out[p++] = a;
            }
        }
    }
    // logdet Sigma_c via Cholesky
    float pl = 1.f;
#pragma unroll
    for (int j = 0; j < KD; j++) {
        float s = S[j][j];
#pragma unroll
        for (int k = 0; k < j; k++) s -= S[j][k] * S[j][k];
        float ljj = sqrtf(s);
        S[j][j] = ljj;
        pl *= ljj;
        float inv = 1.f / ljj;
#pragma unroll
        for (int i = j + 1; i < KD; i++) {
            float si = S[i][j];
#pragma unroll
            for (int k = 0; k < j; k++) si -= S[i][k] * S[j][k];
            S[i][j] = si * inv;
        }
    }
    // store to shared as float4s (+ cc)
    float4* d4 = reinterpret_cast<float4*>(rec);
#pragma unroll
    for (int q = 0; q < 11; q++)
        d4[q] = make_float4(out[4 * q], out[4 * q + 1], out[4 * q + 2], out[4 * q + 3]);
    rec[44] = lad - logf(pl);
}

// ==================== fused main kernel ======================================
__global__ __launch_bounds__(128)
void main_kernel(const float* __restrict__ W,
                 const float* __restrict__ mu_p, const float* __restrict__ sigma_p,
                 const float* __restrict__ omega_child,
                 const float* __restrict__ mu_r, const float* __restrict__ sigma_r,
                 const float* __restrict__ omega_m_child,
                 float* __restrict__ out) {
    const int t = blockIdx.y;
    const int m = threadIdx.x;
    const int n0 = blockIdx.x * NPB;

    // coef loads first (in flight during child phase)
    float4 c4[11];
#pragma unroll
    for (int q = 0; q < 11; q++) c4[q] = g_C4[t][q][m];
    const float dm = g_dm[t][m];
    const unsigned long long* c2 = reinterpret_cast<const unsigned long long*>(c4);

    __shared__ __align__(16) float sh[NPB][48];
    if (m < NPB) {
        if (t == 0) child_work(n0 + m, mu_p, sigma_p, omega_child, &sh[m][0]);
        else        child_work(n0 + m, mu_r, sigma_r, omega_m_child, &sh[m][0]);
    }
    __syncthreads();

    float accf = 0.f;
#pragma unroll 4
    for (int k = 0; k < NPB; k++) {
        float4 a4[11];
#pragma unroll
        for (int q = 0; q < 11; q++)
            a4[q] = reinterpret_cast<const float4*>(&sh[k][0])[q];
        const unsigned long long* a2 = reinterpret_cast<const unsigned long long*>(a4);
        unsigned long long acc0 = 0ull, acc1 = 0ull;
#pragma unroll
        for (int p = 0; p < 22; p += 2) {
            ffma2(acc0, c2[p], a2[p]);
            ffma2(acc1, c2[p + 1], a2[p + 1]);
        }
        float2 s0 = unpack2(acc0);
        float2 s1 = unpack2(acc1);
        float kl = (s0.x + s0.y) + (s1.x + s1.y) + (dm + sh[k][44]);
        accf = fmaf(W[(n0 + k) * MM + m], kl, accf);
    }

    // block reduction, fp64
    double acc = (double)accf;
#pragma unroll
    for (int off = 16; off; off >>= 1)
        acc += __shfl_down_sync(0xffffffffu, acc, off);
    __shared__ double wsum[4];
    __shared__ int islast;
    if ((m & 31) == 0) wsum[m >> 5] = acc;
    __syncthreads();
    if (m == 0) {
        g_part[t][blockIdx.x] = wsum[0] + wsum[1] + wsum[2] + wsum[3];
        __threadfence();
        unsigned int tick = atomicAdd(&g_done, 1u);
        islast = (tick == 2u * NB - 1u) ? 1 : 0;
    }
    __syncthreads();
    if (islast) {
        __threadfence();
        double s0 = (m < NB) ? g_part[0][m] : 0.0;
        double s1 = (m < NB) ? g_part[1][m] : 0.0;
#pragma unroll
        for (int off = 16; off; off >>= 1) {
            s0 += __shfl_down_sync(0xffffffffu, s0, off);
            s1 += __shfl_down_sync(0xffffffffu, s1, off);
        }
        __shared__ double ws0[4], ws1[4];
        if ((m & 31) == 0) { ws0[m >> 5] = s0; ws1[m >> 5] = s1; }
        __syncthreads();
        if (m == 0) {
            double b  = ws0[0] + ws0[1] + ws0[2] + ws0[3];
            double mo = ws1[0] + ws1[1] + ws1[2] + ws1[3];
            out[0] = (float)(b + mo);
            out[1] = (float)b;
            out[2] = (float)mo;
        }
    }
}

// ----------------------------------------------------------------------------
extern "C" void kernel_launch(void* const* d_in, const int* in_sizes, int n_in,
                              void* d_out, int out_size) {
    const float* W              = (const float*)d_in[0];
    const float* mu_p           = (const float*)d_in[1];
    const float* sigma_p        = (const float*)d_in[2];
    const float* mu_q_parent    = (const float*)d_in[3];
    const float* sigma_q_parent = (const float*)d_in[4];
    const float* omega_child    = (const float*)d_in[5];
    const float* omega_parent   = (const float*)d_in[6];
    const float* mu_r           = (const float*)d_in[7];
    const float* sigma_r        = (const float*)d_in[8];
    const float* mu_s_parent    = (const float*)d_in[9];
    const float* sigma_s_parent = (const float*)d_in[10];
    const float* omega_m_child  = (const float*)d_in[11];
    const float* omega_m_parent = (const float*)d_in[12];

    parent_kernel<<<2, MM>>>(mu_q_parent, sigma_q_parent, omega_parent,
                             mu_s_parent, sigma_s_parent, omega_m_parent);
    main_kernel<<<dim3(NB, 2), MM>>>(W, mu_p, sigma_p, omega_child,
                                     mu_r, sigma_r, omega_m_child,
                                     (float*)d_out);
}

// round 6
// speedup vs baseline: 1.0935x; 1.0935x over previous
#include <cuda_runtime.h>
#include <math.h>

#define NN 2048
#define MM 128
#define KD 8
#define K2 64
#define NPACK 36
#define NPB 8             // children per block
#define NB (NN / NPB)     // 256 chunks per t
#define NPRE 34           // precompute blocks: 2 parent + 32 child

// ---------------- scratch --------------------------------------------------
__device__ float4 g_C4[2][11][MM];     // 44 coefs per m: 36 Bp + 8 (-h)
__device__ float  g_dm[2][MM];         // -log|det G| - 4 + 0.5 e.e
__device__ float  g_child[2][NN][48];  // [36 Atilde pk][8 v][c'][3 pad]
__device__ double g_part[2][NB];
__device__ volatile unsigned int g_ready;
__device__ unsigned int g_done;

// ---------------- f32x2 helpers --------------------------------------------
__device__ __forceinline__ void ffma2(unsigned long long& d,
                                      unsigned long long a, unsigned long long b) {
    asm("fma.rn.f32x2 %0, %1, %2, %0;" : "+l"(d) : "l"(a), "l"(b));
}
__device__ __forceinline__ float2 unpack2(unsigned long long v) {
    float2 f;
    asm("mov.b64 {%0, %1}, %2;" : "=f"(f.x), "=f"(f.y) : "l"(v));
    return f;
}

// ==================== parent work (per t,m thread) ===========================
__device__ void parent_work(int t, int m, const float* __restrict__ mup,
                            const float* __restrict__ Sp,
                            const float* __restrict__ Op) {
    float __align__(16) S[KD][KD];
    float __align__(16) O[KD][KD];
    float __align__(16) e[KD];
    {
        const float4* s4 = reinterpret_cast<const float4*>(Sp + (size_t)m * K2);
        const float4* o4 = reinterpret_cast<const float4*>(Op + (size_t)m * K2);
        float4* Sd = reinterpret_cast<float4*>(&S[0][0]);
        float4* Od = reinterpret_cast<float4*>(&O[0][0]);
#pragma unroll
        for (int q = 0; q < 16; q++) { Sd[q] = s4[q]; Od[q] = o4[q]; }
        const float4* m4 = reinterpret_cast<const float4*>(mup + (size_t)m * KD);
        reinterpret_cast<float4*>(e)[0] = m4[0];
        reinterpret_cast<float4*>(e)[1] = m4[1];
    }
    // Cholesky in place (lower triangle -> L)
#pragma unroll
    for (int j = 0; j < KD; j++) {
        float s = S[j][j];
#pragma unroll
        for (int k = 0; k < j; k++) s -= S[j][k] * S[j][k];
        float ljj = sqrtf(s);
        S[j][j] = ljj;
        float inv = 1.f / ljj;
#pragma unroll
        for (int i = j + 1; i < KD; i++) {
            float si = S[i][j];
#pragma unroll
            for (int k = 0; k < j; k++) si -= S[i][k] * S[j][k];
            S[i][j] = si * inv;
        }
    }
    // G = L^{-1} O in place, e := L^{-1} e
#pragma unroll
    for (int i = 0; i < KD; i++) {
        float inv = 1.f / S[i][i];
#pragma unroll
        for (int c = 0; c < KD; c++) {
            float s = O[i][c];
#pragma unroll
            for (int k = 0; k < i; k++) s -= S[i][k] * O[k][c];
            O[i][c] = s * inv;
        }
        float se = e[i];
#pragma unroll
        for (int k = 0; k < i; k++) se -= S[i][k] * e[k];
        e[i] = se * inv;
    }
    float cf[44];
    {
        int p = 0;
#pragma unroll
        for (int i = 0; i < KD; i++) {
#pragma unroll
            for (int j = i; j < KD; j++) {
                float b = 0.f;
#pragma unroll
                for (int k = 0; k < KD; k++) b += O[k][i] * O[k][j];
                cf[p++] = (i == j) ? 0.5f * b : b;
            }
        }
    }
    float ee = 0.f;
#pragma unroll
    for (int i = 0; i < KD; i++) {
        float s = 0.f;
#pragma unroll
        for (int k = 0; k < KD; k++) s += O[k][i] * e[k];
        cf[NPACK + i] = -s;
        ee += e[i] * e[i];
    }
#pragma unroll
    for (int q = 0; q < 11; q++)
        g_C4[t][q][m] = make_float4(cf[4 * q], cf[4 * q + 1], cf[4 * q + 2], cf[4 * q + 3]);
    float pd = 1.f;
#pragma unroll
    for (int j = 0; j < KD; j++) {
        float piv = O[j][j];
        pd *= piv;
        float ip = 1.f / piv;
#pragma unroll
        for (int r = j + 1; r < KD; r++) {
            float f = O[r][j] * ip;
#pragma unroll
            for (int c = j + 1; c < KD; c++) O[r][c] -= f * O[j][c];
        }
    }
    g_dm[t][m] = -logf(fabsf(pd)) - 4.0f + 0.5f * ee;
}

// ==================== child work (per t,n thread) ============================
__device__ void child_work(int t, int n, const float* __restrict__ muc,
                           const float* __restrict__ Sc,
                           const float* __restrict__ Oc) {
    float __align__(16) O[KD][KD];
    float __align__(16) S[KD][KD];
    float __align__(16) mu[KD];
    {
        const float4* s4 = reinterpret_cast<const float4*>(Sc + (size_t)n * K2);
        const float4* o4 = reinterpret_cast<const float4*>(Oc + (size_t)n * K2);
        float4* Sd = reinterpret_cast<float4*>(&S[0][0]);
        float4* Od = reinterpret_cast<float4*>(&O[0][0]);
#pragma unroll
        for (int q = 0; q < 16; q++) { Sd[q] = s4[q]; Od[q] = o4[q]; }
        const float4* m4 = reinterpret_cast<const float4*>(muc + (size_t)n * KD);
        reinterpret_cast<float4*>(mu)[0] = m4[0];
        reinterpret_cast<float4*>(mu)[1] = m4[1];
    }
    // unpivoted Gauss-Jordan inverse; product of pivots = det
    float pd = 1.f;
#pragma unroll
    for (int k = 0; k < KD; k++) {
        float piv = O[k][k];
        pd *= piv;
        float ip = 1.f / piv;
#pragma unroll
        for (int i = 0; i < KD; i++) {
            if (i == k) continue;
            float f = O[i][k] * ip;
#pragma unroll
            for (int j = 0; j < KD; j++)
                if (j != k) O[i][j] -= f * O[k][j];
            O[i][k] = -f;
        }
#pragma unroll
        for (int j = 0; j < KD; j++)
            if (j != k) O[k][j] *= ip;
        O[k][k] = ip;
    }
    float lad = logf(fabsf(pd));

    float out[45];
    float v[KD];
#pragma unroll
    for (int i = 0; i < KD; i++) {
        float s = 0.f;
#pragma unroll
        for (int j = 0; j < KD; j++) s += O[i][j] * mu[j];
        v[i] = s;
        out[NPACK + i] = s;
    }
    {
        int p = 0;
#pragma unroll
        for (int i = 0; i < KD; i++) {
            float trow[KD];
#pragma unroll
            for (int c = 0; c < KD; c++) {
                float s = 0.f;
#pragma unroll
                for (int b = 0; b < KD; b++) s += O[i][b] * S[b][c];
                trow[c] = s;
            }
#pragma unroll
            for (int j = i; j < KD; j++) {
                float a = v[i] * v[j];
#pragma unroll
                for (int c = 0; c < KD; c++) a += trow[c] * O[j][c];
                out[p++] = a;
            }
        }
    }
    float pl = 1.f;
#pragma unroll
    for (int j = 0; j < KD; j++) {
        float s = S[j][j];
#pragma unroll
        for (int k = 0; k < j; k++) s -= S[j][k] * S[j][k];
        float ljj = sqrtf(s);
        S[j][j] = ljj;
        pl *= ljj;
        float inv = 1.f / ljj;
#pragma unroll
        for (int i = j + 1; i < KD; i++) {
            float si = S[i][j];
#pragma unroll
            for (int k = 0; k < j; k++) si -= S[i][k] * S[j][k];
            S[i][j] = si * inv;
        }
    }
    float4* dst = reinterpret_cast<float4*>(&g_child[t][n][0]);
#pragma unroll
    for (int q = 0; q < 11; q++)
        dst[q] = make_float4(out[4 * q], out[4 * q + 1], out[4 * q + 2], out[4 * q + 3]);
    g_child[t][n][44] = lad - logf(pl);
}

// ==================== one fused kernel =======================================
__global__ __launch_bounds__(128, 3)
void main_kernel(const float* __restrict__ W,
                 const float* __restrict__ mu_p, const float* __restrict__ sigma_p,
                 const float* __restrict__ omega_child,
                 const float* __restrict__ mu_q, const float* __restrict__ sigma_q,
                 const float* __restrict__ omega_parent,
                 const float* __restrict__ mu_r, const float* __restrict__ sigma_r,
                 const float* __restrict__ omega_m_child,
                 const float* __restrict__ mu_s, const float* __restrict__ sigma_s,
                 const float* __restrict__ omega_m_parent,
                 float* __restrict__ out) {
    const int m   = threadIdx.x;
    const int t   = blockIdx.y;
    const int bid = blockIdx.y * gridDim.x + blockIdx.x;   // linear; 0..33 launch first

    // ---- phase 1: precompute (first 34 linear bids only; all in wave 1) ----
    if (bid < 2) {
        parent_work(bid, m,
                    (bid == 0) ? mu_q : mu_s,
                    (bid == 0) ? sigma_q : sigma_s,
                    (bid == 0) ? omega_parent : omega_m_parent);
    } else if (bid < NPRE) {
        int gid = (bid - 2) * 128 + m;   // 0..4095
        int tt = gid >> 11;
        int n  = gid & (NN - 1);
        if (tt == 0) child_work(0, n, mu_p, sigma_p, omega_child);
        else         child_work(1, n, mu_r, sigma_r, omega_m_child);
    }
    if (bid < NPRE) {
        __threadfence();
        __syncthreads();
        if (m == 0) atomicAdd((unsigned int*)&g_ready, 1u);
    }

    // ---- wait for all precompute ----
    if (m == 0) {
        while (g_ready < NPRE) { }
    }
    __syncthreads();
    __threadfence();

    // ---- phase 2: pair work for chunk (blockIdx.x, t) ----
    const int n0 = blockIdx.x * NPB;

    float4 c4[11];
#pragma unroll
    for (int q = 0; q < 11; q++) c4[q] = g_C4[t][q][m];
    const float dm = g_dm[t][m];
    const unsigned long long* c2 = reinterpret_cast<const unsigned long long*>(c4);

    __shared__ __align__(16) float sh[NPB][48];
    if (m < NPB * 12) {
        int k = m / 12, q = m % 12;
        reinterpret_cast<float4*>(&sh[k][0])[q] =
            reinterpret_cast<const float4*>(&g_child[t][n0 + k][0])[q];
    }
    __syncthreads();

    float accf = 0.f;
#pragma unroll
    for (int k = 0; k < NPB; k++) {
        const unsigned long long* a2 =
            reinterpret_cast<const unsigned long long*>(&sh[k][0]);
        unsigned long long acc0 = 0ull, acc1 = 0ull;
#pragma unroll
        for (int p = 0; p < 22; p += 2) {
            ffma2(acc0, c2[p], a2[p]);
            ffma2(acc1, c2[p + 1], a2[p + 1]);
        }
        float2 s0 = unpack2(acc0);
        float2 s1 = unpack2(acc1);
        float kl = (s0.x + s0.y) + (s1.x + s1.y) + (dm + sh[k][44]);
        accf = fmaf(W[(n0 + k) * MM + m], kl, accf);
    }

    // ---- fp32 warp reduce -> fp64 block partial ----
#pragma unroll
    for (int off = 16; off; off >>= 1)
        accf += __shfl_down_sync(0xffffffffu, accf, off);
    __shared__ float wsumf[4];
    __shared__ int islast;
    if ((m & 31) == 0) wsumf[m >> 5] = accf;
    __syncthreads();
    if (m == 0) {
        g_part[t][blockIdx.x] =
            (double)wsumf[0] + (double)wsumf[1] + (double)wsumf[2] + (double)wsumf[3];
        __threadfence();
        unsigned int tick = atomicAdd(&g_done, 1u);
        islast = (tick == 2u * NB - 1u) ? 1 : 0;
    }
    __syncthreads();

    // ---- last block: final reduce + output + flag reset ----
    if (islast) {
        __threadfence();
        double s0 = g_part[0][m] + g_part[0][m + 128];
        double s1 = g_part[1][m] + g_part[1][m + 128];
#pragma unroll
        for (int off = 16; off; off >>= 1) {
            s0 += __shfl_down_sync(0xffffffffu, s0, off);
            s1 += __shfl_down_sync(0xffffffffu, s1, off);
        }
        __shared__ double ws0[4], ws1[4];
        if ((m & 31) == 0) { ws0[m >> 5] = s0; ws1[m >> 5] = s1; }
        __syncthreads();
        if (m == 0) {
            double b  = ws0[0] + ws0[1] + ws0[2] + ws0[3];
            double mo = ws1[0] + ws1[1] + ws1[2] + ws1[3];
            out[0] = (float)(b + mo);
            out[1] = (float)b;
            out[2] = (float)mo;
            g_done = 0u;           // reset for next graph replay
            g_ready = 0u;
        }
    }
}

// ----------------------------------------------------------------------------
extern "C" void kernel_launch(void* const* d_in, const int* in_sizes, int n_in,
                              void* d_out, int out_size) {
    const float* W              = (const float*)d_in[0];
    const float* mu_p           = (const float*)d_in[1];
    const float* sigma_p        = (const float*)d_in[2];
    const float* mu_q_parent    = (const float*)d_in[3];
    const float* sigma_q_parent = (const float*)d_in[4];
    const float* omega_child    = (const float*)d_in[5];
    const float* omega_parent   = (const float*)d_in[6];
    const float* mu_r           = (const float*)d_in[7];
    const float* sigma_r        = (const float*)d_in[8];
    const float* mu_s_parent    = (const float*)d_in[9];
    const float* sigma_s_parent = (const float*)d_in[10];
    const float* omega_m_child  = (const float*)d_in[11];
    const float* omega_m_parent = (const float*)d_in[12];

    main_kernel<<<dim3(NB, 2), 128>>>(W,
                                      mu_p, sigma_p, omega_child,
                                      mu_q_parent, sigma_q_parent, omega_parent,
                                      mu_r, sigma_r, omega_m_child,
                                      mu_s_parent, sigma_s_parent, omega_m_parent,
                                      (float*)d_out);
}

// round 7
// speedup vs baseline: 1.2620x; 1.1541x over previous
#include <cuda_runtime.h>
#include <math.h>

#define NN 2048
#define MM 128
#define KD 8
#define K2 64
#define NPACK 36
#define NPB 16            // children per block
#define NB (NN / NPB)     // 128 chunks per t

// ---------------- scratch --------------------------------------------------
__device__ float4 g_C4[2][11][MM];     // 44 coefs per m: 36 Bp + 8 (-h), SoA over m
__device__ float  g_dm[2][MM];         // -log|det G| - 4 + 0.5 e.e
__device__ float  g_child[2][NN][48];  // [36 Atilde pk][8 v][c'][3 pad]
__device__ double g_part[2][NB];
__device__ unsigned int g_done;

// ---------------- f32x2 helpers --------------------------------------------
__device__ __forceinline__ void ffma2(unsigned long long& d,
                                      unsigned long long a, unsigned long long b) {
    asm("fma.rn.f32x2 %0, %1, %2, %0;" : "+l"(d) : "l"(a), "l"(b));
}
__device__ __forceinline__ float2 unpack2(unsigned long long v) {
    float2 f;
    asm("mov.b64 {%0, %1}, %2;" : "=f"(f.x), "=f"(f.y) : "l"(v));
    return f;
}

// ==================== parent work =============================================
__device__ void parent_work(int t, int m, const float* __restrict__ mup,
                            const float* __restrict__ Sp,
                            const float* __restrict__ Op) {
    float __align__(16) S[KD][KD];
    float __align__(16) O[KD][KD];
    float __align__(16) e[KD];
    {
        const float4* s4 = reinterpret_cast<const float4*>(Sp + (size_t)m * K2);
        const float4* o4 = reinterpret_cast<const float4*>(Op + (size_t)m * K2);
        float4* Sd = reinterpret_cast<float4*>(&S[0][0]);
        float4* Od = reinterpret_cast<float4*>(&O[0][0]);
#pragma unroll
        for (int q = 0; q < 16; q++) { Sd[q] = s4[q]; Od[q] = o4[q]; }
        const float4* m4 = reinterpret_cast<const float4*>(mup + (size_t)m * KD);
        reinterpret_cast<float4*>(e)[0] = m4[0];
        reinterpret_cast<float4*>(e)[1] = m4[1];
    }
    // Cholesky in place (lower triangle -> L)
#pragma unroll
    for (int j = 0; j < KD; j++) {
        float s = S[j][j];
#pragma unroll
        for (int k = 0; k < j; k++) s -= S[j][k] * S[j][k];
        float ljj = sqrtf(s);
        S[j][j] = ljj;
        float inv = 1.f / ljj;
#pragma unroll
        for (int i = j + 1; i < KD; i++) {
            float si = S[i][j];
#pragma unroll
            for (int k = 0; k < j; k++) si -= S[i][k] * S[j][k];
            S[i][j] = si * inv;
        }
    }
    // G = L^{-1} O in place, e := L^{-1} e
#pragma unroll
    for (int i = 0; i < KD; i++) {
        float inv = 1.f / S[i][i];
#pragma unroll
        for (int c = 0; c < KD; c++) {
            float s = O[i][c];
#pragma unroll
            for (int k = 0; k < i; k++) s -= S[i][k] * O[k][c];
            O[i][c] = s * inv;
        }
        float se = e[i];
#pragma unroll
        for (int k = 0; k < i; k++) se -= S[i][k] * e[k];
        e[i] = se * inv;
    }
    float cf[44];
    {
        int p = 0;
#pragma unroll
        for (int i = 0; i < KD; i++) {
#pragma unroll
            for (int j = i; j < KD; j++) {
                float b = 0.f;
#pragma unroll
                for (int k = 0; k < KD; k++) b += O[k][i] * O[k][j];
                cf[p++] = (i == j) ? 0.5f * b : b;
            }
        }
    }
    float ee = 0.f;
#pragma unroll
    for (int i = 0; i < KD; i++) {
        float s = 0.f;
#pragma unroll
        for (int k = 0; k < KD; k++) s += O[k][i] * e[k];
        cf[NPACK + i] = -s;
        ee += e[i] * e[i];
    }
#pragma unroll
    for (int q = 0; q < 11; q++)
        g_C4[t][q][m] = make_float4(cf[4 * q], cf[4 * q + 1], cf[4 * q + 2], cf[4 * q + 3]);
    float pd = 1.f;
#pragma unroll
    for (int j = 0; j < KD; j++) {
        float piv = O[j][j];
        pd *= piv;
        float ip = 1.f / piv;
#pragma unroll
        for (int r = j + 1; r < KD; r++) {
            float f = O[r][j] * ip;
#pragma unroll
            for (int c = j + 1; c < KD; c++) O[r][c] -= f * O[j][c];
        }
    }
    g_dm[t][m] = -logf(fabsf(pd)) - 4.0f + 0.5f * ee;
}

// ==================== child work ==============================================
__device__ void child_work(int t, int n, const float* __restrict__ muc,
                           const float* __restrict__ Sc,
                           const float* __restrict__ Oc) {
    float __align__(16) O[KD][KD];
    float __align__(16) S[KD][KD];
    float __align__(16) mu[KD];
    {
        const float4* s4 = reinterpret_cast<const float4*>(Sc + (size_t)n * K2);
        const float4* o4 = reinterpret_cast<const float4*>(Oc + (size_t)n * K2);
        float4* Sd = reinterpret_cast<float4*>(&S[0][0]);
        float4* Od = reinterpret_cast<float4*>(&O[0][0]);
#pragma unroll
        for (int q = 0; q < 16; q++) { Sd[q] = s4[q]; Od[q] = o4[q]; }
        const float4* m4 = reinterpret_cast<const float4*>(muc + (size_t)n * KD);
        reinterpret_cast<float4*>(mu)[0] = m4[0];
        reinterpret_cast<float4*>(mu)[1] = m4[1];
    }
    // unpivoted Gauss-Jordan inverse; product of pivots = det
    float pd = 1.f;
#pragma unroll
    for (int k = 0; k < KD; k++) {
        float piv = O[k][k];
        pd *= piv;
        float ip = 1.f / piv;
#pragma unroll
        for (int i = 0; i < KD; i++) {
            if (i == k) continue;
            float f = O[i][k] * ip;
#pragma unroll
            for (int j = 0; j < KD; j++)
                if (j != k) O[i][j] -= f * O[k][j];
            O[i][k] = -f;
        }
#pragma unroll
        for (int j = 0; j < KD; j++)
            if (j != k) O[k][j] *= ip;
        O[k][k] = ip;
    }
    float lad = logf(fabsf(pd));

    float out[45];
    float v[KD];
#pragma unroll
    for (int i = 0; i < KD; i++) {
        float s = 0.f;
#pragma unroll
        for (int j = 0; j < KD; j++) s += O[i][j] * mu[j];
        v[i] = s;
        out[NPACK + i] = s;
    }
    {
        int p = 0;
#pragma unroll
        for (int i = 0; i < KD; i++) {
            float trow[KD];
#pragma unroll
            for (int c = 0; c < KD; c++) {
                float s = 0.f;
#pragma unroll
                for (int b = 0; b < KD; b++) s += O[i][b] * S[b][c];
                trow[c] = s;
            }
#pragma unroll
            for (int j = i; j < KD; j++) {
                float a = v[i] * v[j];
#pragma unroll
                for (int c = 0; c < KD; c++) a += trow[c] * O[j][c];
                out[p++] = a;
            }
        }
    }
    float pl = 1.f;
#pragma unroll
    for (int j = 0; j < KD; j++) {
        float s = S[j][j];
#pragma unroll
        for (int k = 0; k < j; k++) s -= S[j][k] * S[j][k];
        float ljj = sqrtf(s);
        S[j][j] = ljj;
        pl *= ljj;
        float inv = 1.f / ljj;
#pragma unroll
        for (int i = j + 1; i < KD; i++) {
            float si = S[i][j];
#pragma unroll
            for (int k = 0; k < j; k++) si -= S[i][k] * S[j][k];
            S[i][j] = si * inv;
        }
    }
    float4* dst = reinterpret_cast<float4*>(&g_child[t][n][0]);
#pragma unroll
    for (int q = 0; q < 11; q++)
        dst[q] = make_float4(out[4 * q], out[4 * q + 1], out[4 * q + 2], out[4 * q + 3]);
    g_child[t][n][44] = lad - logf(pl);
}

// ==================== precompute kernel (proven R4 layout) ===================
__global__ __launch_bounds__(32)
void precompute_kernel(const float* __restrict__ mu_p, const float* __restrict__ sigma_p,
                       const float* __restrict__ omega_child,
                       const float* __restrict__ mu_q, const float* __restrict__ sigma_q,
                       const float* __restrict__ omega_parent,
                       const float* __restrict__ mu_r, const float* __restrict__ sigma_r,
                       const float* __restrict__ omega_m_child,
                       const float* __restrict__ mu_s, const float* __restrict__ sigma_s,
                       const float* __restrict__ omega_m_parent) {
    int bid = blockIdx.x;
    int tid = threadIdx.x;
    if (bid == 0 && tid == 0) g_done = 0u;
    if (bid < 8) {
        int gid = bid * 32 + tid;   // 256 = 2 t x 128 m
        int t = gid >> 7;
        int m = gid & (MM - 1);
        if (t == 0) parent_work(0, m, mu_q, sigma_q, omega_parent);
        else        parent_work(1, m, mu_s, sigma_s, omega_m_parent);
    } else {
        int gid = (bid - 8) * 32 + tid;  // 4096 = 2 t x 2048 n
        int t = gid >> 11;
        int n = gid & (NN - 1);
        if (t == 0) child_work(0, n, mu_p, sigma_p, omega_child);
        else        child_work(1, n, mu_r, sigma_r, omega_m_child);
    }
}

// ==================== pair kernel =============================================
__global__ __launch_bounds__(128)
void pair_kernel(const float* __restrict__ W, float* __restrict__ out) {
    const int t = blockIdx.y;
    const int m = threadIdx.x;
    const int n0 = blockIdx.x * NPB;

    // coef prologue: 11 coalesced LDG.128 + dm
    float4 c4[11];
#pragma unroll
    for (int q = 0; q < 11; q++) c4[q] = g_C4[t][q][m];
    const float dm = g_dm[t][m];
    const unsigned long long* c2 = reinterpret_cast<const unsigned long long*>(c4);

    // stage all 16 child records into shared (float4 coalesced, 192 float4)
    __shared__ __align__(16) float4 sh4[NPB * 12];
#pragma unroll
    for (int q = m; q < NPB * 12; q += 128) {
        int k = q / 12, r = q % 12;
        sh4[q] = reinterpret_cast<const float4*>(&g_child[t][n0 + k][0])[r];
    }
    // W prefetch: 16 coalesced LDG.32
    float wv[NPB];
#pragma unroll
    for (int k = 0; k < NPB; k++) wv[k] = W[(n0 + k) * MM + m];
    __syncthreads();

    float accf = 0.f;
#pragma unroll
    for (int k = 0; k < NPB; k++) {
        float4 a4[11];
#pragma unroll
        for (int q = 0; q < 11; q++) a4[q] = sh4[k * 12 + q];
        const unsigned long long* a2 = reinterpret_cast<const unsigned long long*>(a4);
        unsigned long long acc0 = 0ull, acc1 = 0ull;
#pragma unroll
        for (int p = 0; p < 22; p += 2) {
            ffma2(acc0, c2[p], a2[p]);
            ffma2(acc1, c2[p + 1], a2[p + 1]);
        }
        float2 s0 = unpack2(acc0);
        float2 s1 = unpack2(acc1);
        float cc = reinterpret_cast<const float*>(&sh4[k * 12])[44];
        float kl = (s0.x + s0.y) + (s1.x + s1.y) + (dm + cc);
        accf = fmaf(wv[k], kl, accf);
    }

    // fp32 warp reduce -> fp64 block partial, ticket finalize
#pragma unroll
    for (int off = 16; off; off >>= 1)
        accf += __shfl_down_sync(0xffffffffu, accf, off);
    __shared__ float wsumf[4];
    __shared__ int islast;
    if ((m & 31) == 0) wsumf[m >> 5] = accf;
    __syncthreads();
    if (m == 0) {
        g_part[t][blockIdx.x] =
            (double)wsumf[0] + (double)wsumf[1] + (double)wsumf[2] + (double)wsumf[3];
        __threadfence();
        unsigned int tick = atomicAdd(&g_done, 1u);
        islast = (tick == 2u * NB - 1u) ? 1 : 0;
    }
    __syncthreads();
    if (islast) {
        __threadfence();
        double s0 = (m < NB) ? g_part[0][m] : 0.0;
        double s1 = (m < NB) ? g_part[1][m] : 0.0;
#pragma unroll
        for (int off = 16; off; off >>= 1) {
            s0 += __shfl_down_sync(0xffffffffu, s0, off);
            s1 += __shfl_down_sync(0xffffffffu, s1, off);
        }
        __shared__ double ws0[4], ws1[4];
        if ((m & 31) == 0) { ws0[m >> 5] = s0; ws1[m >> 5] = s1; }
        __syncthreads();
        if (m == 0) {
            double b  = ws0[0] + ws0[1] + ws0[2] + ws0[3];
            double mo = ws1[0] + ws1[1] + ws1[2] + ws1[3];
            out[0] = (float)(b + mo);
            out[1] = (float)b;
            out[2] = (float)mo;
        }
    }
}

// ----------------------------------------------------------------------------
extern "C" void kernel_launch(void* const* d_in, const int* in_sizes, int n_in,
                              void* d_out, int out_size) {
    const float* W              = (const float*)d_in[0];
    const float* mu_p           = (const float*)d_in[1];
    const float* sigma_p        = (const float*)d_in[2];
    const float* mu_q_parent    = (const float*)d_in[3];
    const float* sigma_q_parent = (const float*)d_in[4];
    const float* omega_child    = (const float*)d_in[5];
    const float* omega_parent   = (const float*)d_in[6];
    const float* mu_r           = (const float*)d_in[7];
    const float* sigma_r        = (const float*)d_in[8];
    const float* mu_s_parent    = (const float*)d_in[9];
    const float* sigma_s_parent = (const float*)d_in[10];
    const float* omega_m_child  = (const float*)d_in[11];
    const float* omega_m_parent = (const float*)d_in[12];

    precompute_kernel<<<136, 32>>>(mu_p, sigma_p, omega_child,
                                   mu_q_parent, sigma_q_parent, omega_parent,
                                   mu_r, sigma_r, omega_m_child,
                                   mu_s_parent, sigma_s_parent, omega_m_parent);
    pair_kernel<<<dim3(NB, 2), MM>>>(W, (float*)d_out);
}

// round 8
// speedup vs baseline: 1.4147x; 1.1210x over previous
#include <cuda_runtime.h>
#include <math.h>

#define NN 2048
#define MM 128
#define KD 8
#define K2 64
#define NPACK 36
#define NPB 4             // children per block
#define NB (NN / NPB)     // 512 chunks per t

// ---------------- scratch --------------------------------------------------
__device__ float4 g_C4[2][11][MM];     // 44 coefs per m: 36 Bp + 8 (-h), SoA over m
__device__ float  g_dm[2][MM];         // -log|det G| - 4 + 0.5 e.e
__device__ float  g_child[2][NN][48];  // [36 Atilde pk][8 v][c'][3 pad]
__device__ double g_part[2][NB];
__device__ unsigned int g_done;

// ---------------- f32x2 helpers --------------------------------------------
__device__ __forceinline__ void ffma2(unsigned long long& d,
                                      unsigned long long a, unsigned long long b) {
    asm("fma.rn.f32x2 %0, %1, %2, %0;" : "+l"(d) : "l"(a), "l"(b));
}
__device__ __forceinline__ float2 unpack2(unsigned long long v) {
    float2 f;
    asm("mov.b64 {%0, %1}, %2;" : "=f"(f.x), "=f"(f.y) : "l"(v));
    return f;
}

// ==================== parent work =============================================
__device__ void parent_work(int t, int m, const float* __restrict__ mup,
                            const float* __restrict__ Sp,
                            const float* __restrict__ Op) {
    float __align__(16) S[KD][KD];
    float __align__(16) O[KD][KD];
    float __align__(16) e[KD];
    {
        const float4* s4 = reinterpret_cast<const float4*>(Sp + (size_t)m * K2);
        const float4* o4 = reinterpret_cast<const float4*>(Op + (size_t)m * K2);
        float4* Sd = reinterpret_cast<float4*>(&S[0][0]);
        float4* Od = reinterpret_cast<float4*>(&O[0][0]);
#pragma unroll
        for (int q = 0; q < 16; q++) { Sd[q] = s4[q]; Od[q] = o4[q]; }
        const float4* m4 = reinterpret_cast<const float4*>(mup + (size_t)m * KD);
        reinterpret_cast<float4*>(e)[0] = m4[0];
        reinterpret_cast<float4*>(e)[1] = m4[1];
    }
    // Cholesky in place (lower triangle -> L)
#pragma unroll
    for (int j = 0; j < KD; j++) {
        float s = S[j][j];
#pragma unroll
        for (int k = 0; k < j; k++) s -= S[j][k] * S[j][k];
        float ljj = sqrtf(s);
        S[j][j] = ljj;
        float inv = 1.f / ljj;
#pragma unroll
        for (int i = j + 1; i < KD; i++) {
            float si = S[i][j];
#pragma unroll
            for (int k = 0; k < j; k++) si -= S[i][k] * S[j][k];
            S[i][j] = si * inv;
        }
    }
    // G = L^{-1} O in place, e := L^{-1} e
#pragma unroll
    for (int i = 0; i < KD; i++) {
        float inv = 1.f / S[i][i];
#pragma unroll
        for (int c = 0; c < KD; c++) {
            float s = O[i][c];
#pragma unroll
            for (int k = 0; k < i; k++) s -= S[i][k] * O[k][c];
            O[i][c] = s * inv;
        }
        float se = e[i];
#pragma unroll
        for (int k = 0; k < i; k++) se -= S[i][k] * e[k];
        e[i] = se * inv;
    }
    float cf[44];
    {
        int p = 0;
#pragma unroll
        for (int i = 0; i < KD; i++) {
#pragma unroll
            for (int j = i; j < KD; j++) {
                float b = 0.f;
#pragma unroll
                for (int k = 0; k < KD; k++) b += O[k][i] * O[k][j];
                cf[p++] = (i == j) ? 0.5f * b : b;
            }
        }
    }
    float ee = 0.f;
#pragma unroll
    for (int i = 0; i < KD; i++) {
        float s = 0.f;
#pragma unroll
        for (int k = 0; k < KD; k++) s += O[k][i] * e[k];
        cf[NPACK + i] = -s;
        ee += e[i] * e[i];
    }
#pragma unroll
    for (int q = 0; q < 11; q++)
        g_C4[t][q][m] = make_float4(cf[4 * q], cf[4 * q + 1], cf[4 * q + 2], cf[4 * q + 3]);
    float pd = 1.f;
#pragma unroll
    for (int j = 0; j < KD; j++) {
        float piv = O[j][j];
        pd *= piv;
        float ip = 1.f / piv;
#pragma unroll
        for (int r = j + 1; r < KD; r++) {
            float f = O[r][j] * ip;
#pragma unroll
            for (int c = j + 1; c < KD; c++) O[r][c] -= f * O[j][c];
        }
    }
    g_dm[t][m] = -logf(fabsf(pd)) - 4.0f + 0.5f * ee;
}

// ==================== child work ==============================================
__device__ void child_work(int t, int n, const float* __restrict__ muc,
                           const float* __restrict__ Sc,
                           const float* __restrict__ Oc) {
    float __align__(16) O[KD][KD];
    float __align__(16) S[KD][KD];
    float __align__(16) mu[KD];
    {
        const float4* s4 = reinterpret_cast<const float4*>(Sc + (size_t)n * K2);
        const float4* o4 = reinterpret_cast<const float4*>(Oc + (size_t)n * K2);
        float4* Sd = reinterpret_cast<float4*>(&S[0][0]);
        float4* Od = reinterpret_cast<float4*>(&O[0][0]);
#pragma unroll
        for (int q = 0; q < 16; q++) { Sd[q] = s4[q]; Od[q] = o4[q]; }
        const float4* m4 = reinterpret_cast<const float4*>(muc + (size_t)n * KD);
        reinterpret_cast<float4*>(mu)[0] = m4[0];
        reinterpret_cast<float4*>(mu)[1] = m4[1];
    }
    // unpivoted Gauss-Jordan inverse; product of pivots = det
    float pd = 1.f;
#pragma unroll
    for (int k = 0; k < KD; k++) {
        float piv = O[k][k];
        pd *= piv;
        float ip = 1.f / piv;
#pragma unroll
        for (int i = 0; i < KD; i++) {
            if (i == k) continue;
            float f = O[i][k] * ip;
#pragma unroll
            for (int j = 0; j < KD; j++)
                if (j != k) O[i][j] -= f * O[k][j];
            O[i][k] = -f;
        }
#pragma unroll
        for (int j = 0; j < KD; j++)
            if (j != k) O[k][j] *= ip;
        O[k][k] = ip;
    }
    float lad = logf(fabsf(pd));

    float out[45];
    float v[KD];
#pragma unroll
    for (int i = 0; i < KD; i++) {
        float s = 0.f;
#pragma unroll
        for (int j = 0; j < KD; j++) s += O[i][j] * mu[j];
        v[i] = s;
        out[NPACK + i] = s;
    }
    {
        int p = 0;
#pragma unroll
        for (int i = 0; i < KD; i++) {
            float trow[KD];
#pragma unroll
            for (int c = 0; c < KD; c++) {
                float s = 0.f;
#pragma unroll
                for (int b = 0; b < KD; b++) s += O[i][b] * S[b][c];
                trow[c] = s;
            }
#pragma unroll
            for (int j = i; j < KD; j++) {
                float a = v[i] * v[j];
#pragma unroll
                for (int c = 0; c < KD; c++) a += trow[c] * O[j][c];
                out[p++] = a;
            }
        }
    }
    float pl = 1.f;
#pragma unroll
    for (int j = 0; j < KD; j++) {
        float s = S[j][j];
#pragma unroll
        for (int k = 0; k < j; k++) s -= S[j][k] * S[j][k];
        float ljj = sqrtf(s);
        S[j][j] = ljj;
        pl *= ljj;
        float inv = 1.f / ljj;
#pragma unroll
        for (int i = j + 1; i < KD; i++) {
            float si = S[i][j];
#pragma unroll
            for (int k = 0; k < j; k++) si -= S[i][k] * S[j][k];
            S[i][j] = si * inv;
        }
    }
    float4* dst = reinterpret_cast<float4*>(&g_child[t][n][0]);
#pragma unroll
    for (int q = 0; q < 11; q++)
        dst[q] = make_float4(out[4 * q], out[4 * q + 1], out[4 * q + 2], out[4 * q + 3]);
    g_child[t][n][44] = lad - logf(pl);
}

// ==================== precompute kernel =======================================
__global__ __launch_bounds__(32)
void precompute_kernel(const float* __restrict__ mu_p, const float* __restrict__ sigma_p,
                       const float* __restrict__ omega_child,
                       const float* __restrict__ mu_q, const float* __restrict__ sigma_q,
                       const float* __restrict__ omega_parent,
                       const float* __restrict__ mu_r, const float* __restrict__ sigma_r,
                       const float* __restrict__ omega_m_child,
                       const float* __restrict__ mu_s, const float* __restrict__ sigma_s,
                       const float* __restrict__ omega_m_parent) {
    int bid = blockIdx.x;
    int tid = threadIdx.x;
    if (bid == 0 && tid == 0) g_done = 0u;
    if (bid < 8) {
        int gid = bid * 32 + tid;   // 256 = 2 t x 128 m
        int t = gid >> 7;
        int m = gid & (MM - 1);
        if (t == 0) parent_work(0, m, mu_q, sigma_q, omega_parent);
        else        parent_work(1, m, mu_s, sigma_s, omega_m_parent);
    } else {
        int gid = (bid - 8) * 32 + tid;  // 4096 = 2 t x 2048 n
        int t = gid >> 11;
        int n = gid & (NN - 1);
        if (t == 0) child_work(0, n, mu_p, sigma_p, omega_child);
        else        child_work(1, n, mu_r, sigma_r, omega_m_child);
    }
}

// ==================== pair kernel =============================================
__global__ __launch_bounds__(128)
void pair_kernel(const float* __restrict__ W, float* __restrict__ out) {
    const int t = blockIdx.y;
    const int m = threadIdx.x;
    const int n0 = blockIdx.x * NPB;

    // W prefetch first (DRAM, longest latency): 4 coalesced LDG.32
    float wv[NPB];
#pragma unroll
    for (int k = 0; k < NPB; k++) wv[k] = W[(n0 + k) * MM + m];

    // coef prologue: 11 coalesced LDG.128 + dm (L2)
    float4 c4[11];
#pragma unroll
    for (int q = 0; q < 11; q++) c4[q] = g_C4[t][q][m];
    const float dm = g_dm[t][m];
    const unsigned long long* c2 = reinterpret_cast<const unsigned long long*>(c4);

    // stage 4 child records into shared (48 float4, coalesced)
    __shared__ __align__(16) float4 sh4[NPB * 12];
    if (m < NPB * 12) {
        int k = m / 12, r = m % 12;
        sh4[m] = reinterpret_cast<const float4*>(&g_child[t][n0 + k][0])[r];
    }
    __syncthreads();

    float accf = 0.f;
#pragma unroll
    for (int k = 0; k < NPB; k++) {
        const unsigned long long* a2 =
            reinterpret_cast<const unsigned long long*>(&sh4[k * 12]);
        unsigned long long acc0 = 0ull, acc1 = 0ull;
#pragma unroll
        for (int p = 0; p < 22; p += 2) {
            ffma2(acc0, c2[p], a2[p]);
            ffma2(acc1, c2[p + 1], a2[p + 1]);
        }
        float2 s0 = unpack2(acc0);
        float2 s1 = unpack2(acc1);
        float cc = reinterpret_cast<const float*>(&sh4[k * 12])[44];
        float kl = (s0.x + s0.y) + (s1.x + s1.y) + (dm + cc);
        accf = fmaf(wv[k], kl, accf);
    }

    // fp32 warp reduce -> fp64 block partial, ticket finalize
#pragma unroll
    for (int off = 16; off; off >>= 1)
        accf += __shfl_down_sync(0xffffffffu, accf, off);
    __shared__ float wsumf[4];
    __shared__ int islast;
    if ((m & 31) == 0) wsumf[m >> 5] = accf;
    __syncthreads();
    if (m == 0) {
        g_part[t][blockIdx.x] =
            (double)wsumf[0] + (double)wsumf[1] + (double)wsumf[2] + (double)wsumf[3];
        __threadfence();
        unsigned int tick = atomicAdd(&g_done, 1u);
        islast = (tick == 2u * NB - 1u) ? 1 : 0;
    }
    __syncthreads();
    if (islast) {
        __threadfence();
        double s0 = g_part[0][m] + g_part[0][m + 128] +
                    g_part[0][m + 256] + g_part[0][m + 384];
        double s1 = g_part[1][m] + g_part[1][m + 128] +
                    g_part[1][m + 256] + g_part[1][m + 384];
#pragma unroll
        for (int off = 16; off; off >>= 1) {
            s0 += __shfl_down_sync(0xffffffffu, s0, off);
            s1 += __shfl_down_sync(0xffffffffu, s1, off);
        }
        __shared__ double ws0[4], ws1[4];
        if ((m & 31) == 0) { ws0[m >> 5] = s0; ws1[m >> 5] = s1; }
        __syncthreads();
        if (m == 0) {
            double b  = ws0[0] + ws0[1] + ws0[2] + ws0[3];
            double mo = ws1[0] + ws1[1] + ws1[2] + ws1[3];
            out[0] = (float)(b + mo);
            out[1] = (float)b;
            out[2] = (float)mo;
        }
    }
}

// ----------------------------------------------------------------------------
extern "C" void kernel_launch(void* const* d_in, const int* in_sizes, int n_in,
                              void* d_out, int out_size) {
    const float* W              = (const float*)d_in[0];
    const float* mu_p           = (const float*)d_in[1];
    const float* sigma_p        = (const float*)d_in[2];
    const float* mu_q_parent    = (const float*)d_in[3];
    const float* sigma_q_parent = (const float*)d_in[4];
    const float* omega_child    = (const float*)d_in[5];
    const float* omega_parent   = (const float*)d_in[6];
    const float* mu_r           = (const float*)d_in[7];
    const float* sigma_r        = (const float*)d_in[8];
    const float* mu_s_parent    = (const float*)d_in[9];
    const float* sigma_s_parent = (const float*)d_in[10];
    const float* omega_m_child  = (const float*)d_in[11];
    const float* omega_m_parent = (const float*)d_in[12];

    precompute_kernel<<<136, 32>>>(mu_p, sigma_p, omega_child,
                                   mu_q_parent, sigma_q_parent, omega_parent,
                                   mu_r, sigma_r, omega_m_child,
                                   mu_s_parent, sigma_s_parent, omega_m_parent);
    pair_kernel<<<dim3(NB, 2), MM>>>(W, (float*)d_out);
}